// round 8
// baseline (speedup 1.0000x reference)
#include <cuda_runtime.h>
#include <cuda_fp16.h>
#include <cstdint>

#define N_NODES   100000
#define DIM       512
#define TILE_M    64
#define TILE_N    256                // per CTA; cluster of 2 covers 512
#define KCH       64                 // K halfs per chunk (128B per row)
#define N_CHUNKS  8
#define THREADS   256
#define NUM_TILES ((N_NODES + TILE_M - 1) / TILE_M)   // 1563
#define GRID      (NUM_TILES * 2)    // 3126, cluster pairs (2t, 2t+1)

// XOR-swizzled rows: 128B, granule g at (g ^ (row&7))*16
#define A_STAGE   8192               // 64 rows x 128B
#define B_STAGE   32768              // 256 rows x 128B

#define SM_BIAS   0                  // 256 f32
#define SM_GAMMA  1024
#define SM_BETA   2048
#define SM_RSUM   3072               // [64][4] f32
#define SM_RSQ    4096
#define SM_PART   5120               // [64][2] f32 (exchange buffer)
#define SM_MEAN   5632               // [64] f32
#define SM_RSTD   5888
#define SM_A      6144               // 2 stages
#define SM_B      22528              // 3 stages (1024-aligned)
#define SMEM_TOTAL (SM_B + 3 * B_STAGE)   // 120832

#define OUT_STRIDE_W 264             // epilogue staging stride (words)

__device__ __half g_Wh[512 * 512];   // pre-converted W (512KB, L2-resident)

static __device__ __forceinline__ uint32_t smem_u32(const void* p) {
    uint32_t a;
    asm("{ .reg .u64 t; cvta.to.shared.u64 t, %1; cvt.u32.u64 %0, t; }" : "=r"(a) : "l"(p));
    return a;
}

#define LDSM4(r, a) \
    asm volatile("ldmatrix.sync.aligned.m8n8.x4.shared.b16 {%0,%1,%2,%3}, [%4];" \
        : "=r"((r)[0]), "=r"((r)[1]), "=r"((r)[2]), "=r"((r)[3]) : "r"(a))

static __device__ __forceinline__ void mma_f16(float* d, const uint32_t* a,
                                               uint32_t b0, uint32_t b1) {
    asm volatile(
        "mma.sync.aligned.m16n8k16.row.col.f32.f16.f16.f32 "
        "{%0,%1,%2,%3}, {%4,%5,%6,%7}, {%8,%9}, {%0,%1,%2,%3};"
        : "+f"(d[0]), "+f"(d[1]), "+f"(d[2]), "+f"(d[3])
        : "r"(a[0]), "r"(a[1]), "r"(a[2]), "r"(a[3]), "r"(b0), "r"(b1));
}

static __device__ __forceinline__ void cp16(uint32_t dst, const void* src) {
    asm volatile("cp.async.cg.shared.global [%0], [%1], 16;" :: "r"(dst), "l"(src));
}

#define CLUSTER_SYNC() do { \
    asm volatile("barrier.cluster.arrive.aligned;" ::: "memory"); \
    asm volatile("barrier.cluster.wait.aligned;" ::: "memory"); \
} while (0)

// B chunk: 256 rows x 128B fp16 from g_Wh (rows ncol0..+256), XOR-swizzled
static __device__ __forceinline__ void load_B(int kc, uint32_t b_base, int tid, int ncol0) {
#pragma unroll
    for (int it = 0; it < 8; it++) {
        int id  = it * THREADS + tid;
        int row = id >> 3, j = id & 7;
        cp16(b_base + (uint32_t)(row * 128 + ((j ^ (row & 7)) << 4)),
             g_Wh + (size_t)(ncol0 + row) * DIM + kc * KCH + j * 8);
    }
}

// A chunk LDG: thread -> row tid>>2, 16 f32 at col (tid&3)*16
static __device__ __forceinline__ void ldg_A(const float* __restrict__ x,
                                             int m0, int kc, int tid, float4* r) {
    int row = tid >> 2;
    int gr  = m0 + row;
    if (gr > N_NODES - 1) gr = N_NODES - 1;   // clamped rows never stored
    const float* p = x + (size_t)gr * DIM + kc * KCH + (tid & 3) * 16;
    r[0] = *(const float4*)(p);
    r[1] = *(const float4*)(p + 4);
    r[2] = *(const float4*)(p + 8);
    r[3] = *(const float4*)(p + 12);
}

// convert + store A chunk (16 f32 -> 2 granules), XOR-swizzled
static __device__ __forceinline__ void sts_A(uint32_t a_base, int tid, const float4* r) {
    int row = tid >> 2, jj = (tid & 3) * 2;
    uint32_t base = a_base + (uint32_t)(row * 128);
    uint32_t a0 = base + (uint32_t)((jj ^ (row & 7)) << 4);
    uint32_t a1 = base + (uint32_t)(((jj + 1) ^ (row & 7)) << 4);
    __half2 h0 = __floats2half2_rn(r[0].x, r[0].y);
    __half2 h1 = __floats2half2_rn(r[0].z, r[0].w);
    __half2 h2 = __floats2half2_rn(r[1].x, r[1].y);
    __half2 h3 = __floats2half2_rn(r[1].z, r[1].w);
    asm volatile("st.shared.v4.b32 [%0], {%1,%2,%3,%4};" :: "r"(a0),
                 "r"(*(uint32_t*)&h0), "r"(*(uint32_t*)&h1),
                 "r"(*(uint32_t*)&h2), "r"(*(uint32_t*)&h3) : "memory");
    __half2 h4 = __floats2half2_rn(r[2].x, r[2].y);
    __half2 h5 = __floats2half2_rn(r[2].z, r[2].w);
    __half2 h6 = __floats2half2_rn(r[3].x, r[3].y);
    __half2 h7 = __floats2half2_rn(r[3].z, r[3].w);
    asm volatile("st.shared.v4.b32 [%0], {%1,%2,%3,%4};" :: "r"(a1),
                 "r"(*(uint32_t*)&h4), "r"(*(uint32_t*)&h5),
                 "r"(*(uint32_t*)&h6), "r"(*(uint32_t*)&h7) : "memory");
}

__global__ void wconv_kernel(const float* __restrict__ W) {
    int i = (blockIdx.x * blockDim.x + threadIdx.x) * 4;
    float4 v = *(const float4*)(W + i);
    __half2 h0 = __floats2half2_rn(v.x, v.y);
    __half2 h1 = __floats2half2_rn(v.z, v.w);
    *(__half2*)(g_Wh + i)     = h0;
    *(__half2*)(g_Wh + i + 2) = h1;
}

__global__ void __launch_bounds__(THREADS, 1) __cluster_dims__(2, 1, 1)
fused_gemm_ln_lrelu(const float* __restrict__ x,
                    const float* __restrict__ bias, const float* __restrict__ gamma,
                    const float* __restrict__ beta, float* __restrict__ out) {
    extern __shared__ __align__(1024) char smem[];
    const uint32_t sb = smem_u32(smem);
    const int tid  = threadIdx.x;
    const int lane = tid & 31;
    const int wid  = tid >> 5;          // 0..7
    const int q    = lane & 3;
    const int g    = lane >> 2;
    const int mh   = wid >> 2;          // M half: rows [32*mh, +32)
    const int nw   = wid & 3;           // N slice: local cols [64*nw, +64)
    const int rank = blockIdx.x & 1;    // cluster CTA rank
    const int peer = rank ^ 1;
    const int m0   = (blockIdx.x >> 1) * TILE_M;
    const int ncol0 = rank * TILE_N;    // global col base

    ((float*)(smem + SM_BIAS))[tid]  = bias[ncol0 + tid];
    ((float*)(smem + SM_GAMMA))[tid] = gamma[ncol0 + tid];
    ((float*)(smem + SM_BETA))[tid]  = beta[ncol0 + tid];

    float acc[2][8][4];
#pragma unroll
    for (int mt = 0; mt < 2; mt++)
#pragma unroll
        for (int nt = 0; nt < 8; nt++)
#pragma unroll
            for (int u = 0; u < 4; u++) acc[mt][nt][u] = 0.f;

    // -------- per-lane ldmatrix address components --------
    const int mr0 = mh * 32 + (lane & 15);        // mt=0 row
    const int mr1 = mr0 + 16;                     // mt=1 row
    const int agsel = lane >> 4;                  // 0/1 (k-low/high granule)
    const uint32_t aoff0 = (uint32_t)(mr0 * 128);
    const uint32_t aoff1 = (uint32_t)(mr1 * 128);
    const int m7_0 = mr0 & 7, m7_1 = mr1 & 7;
    const int wb = nw * 64;                       // local col base of warp
    int n7[4];
    uint32_t boff[4];
    const int bgsel = (lane >> 3) & 1;
#pragma unroll
    for (int p = 0; p < 4; p++) {
        int nr = wb + p * 16 + (lane & 7) + ((lane >> 4) << 3);
        n7[p] = nr & 7;
        boff[p] = (uint32_t)(nr * 128);
    }

    const uint32_t ab = sb + SM_A;
    const uint32_t bb = sb + SM_B;

    // -------- prologue --------
    float4 r[4];
    ldg_A(x, m0, 0, tid, r);
    load_B(0, bb, tid, ncol0);
    asm volatile("cp.async.commit_group;" ::: "memory");
    sts_A(ab, tid, r);
    ldg_A(x, m0, 1, tid, r);
    load_B(1, bb + B_STAGE, tid, ncol0);
    asm volatile("cp.async.commit_group;" ::: "memory");

    int bidx = 0;   // B stage of current chunk

#pragma unroll 1
    for (int i = 0; i < N_CHUNKS; i++) {
        if (i < N_CHUNKS - 1) asm volatile("cp.async.wait_group 1;" ::: "memory");
        else                  asm volatile("cp.async.wait_group 0;" ::: "memory");
        __syncthreads();   // B(i),A(i) visible; stages for (i+2)/(i+1) drained

        const uint32_t SA  = ab + (uint32_t)(i & 1) * A_STAGE;
        const uint32_t SBs = bb + (uint32_t)bidx * B_STAGE;

        // prime fragment pipeline (ks=0)
        uint32_t af[2][2][4], bf[2][4][4];
        LDSM4(af[0][0], SA + aoff0 + (uint32_t)((agsel ^ m7_0) << 4));
        LDSM4(af[0][1], SA + aoff1 + (uint32_t)((agsel ^ m7_1) << 4));
#pragma unroll
        for (int p = 0; p < 4; p++)
            LDSM4(bf[0][p], SBs + boff[p] + (uint32_t)((bgsel ^ n7[p]) << 4));

        // issue next loads into drained stages
        if (i + 2 < N_CHUNKS) {
            int b2 = bidx + 2; if (b2 >= 3) b2 -= 3;
            load_B(i + 2, bb + (uint32_t)b2 * B_STAGE, tid, ncol0);
            asm volatile("cp.async.commit_group;" ::: "memory");
        }
        if (i + 1 < N_CHUNKS) {
            sts_A(ab + (uint32_t)((i + 1) & 1) * A_STAGE, tid, r);
            if (i + 2 < N_CHUNKS) ldg_A(x, m0, i + 2, tid, r);
        }

        // -------- ks-pipelined compute: 4 ks steps of k16 --------
#pragma unroll
        for (int ks = 0; ks < 4; ks++) {
            const int cur = ks & 1, nxt = cur ^ 1;
            if (ks < 3) {
                const int c2 = 2 * (ks + 1);
                LDSM4(af[nxt][0], SA + aoff0 + (uint32_t)(((c2 + agsel) ^ m7_0) << 4));
                LDSM4(af[nxt][1], SA + aoff1 + (uint32_t)(((c2 + agsel) ^ m7_1) << 4));
#pragma unroll
                for (int p = 0; p < 4; p++)
                    LDSM4(bf[nxt][p], SBs + boff[p] + (uint32_t)(((c2 + bgsel) ^ n7[p]) << 4));
            }
#pragma unroll
            for (int mt = 0; mt < 2; mt++)
#pragma unroll
                for (int p = 0; p < 4; p++) {
                    mma_f16(acc[mt][2 * p],     af[cur][mt], bf[cur][p][0], bf[cur][p][1]);
                    mma_f16(acc[mt][2 * p + 1], af[cur][mt], bf[cur][p][2], bf[cur][p][3]);
                }
        }

        if (++bidx == 3) bidx = 0;
    }

    // ---------------- epilogue ----------------
    const float* bs = (const float*)(smem + SM_BIAS);
    const float* gs = (const float*)(smem + SM_GAMMA);
    const float* es = (const float*)(smem + SM_BETA);
    float* rsum  = (float*)(smem + SM_RSUM);
    float* rsq   = (float*)(smem + SM_RSQ);
    float* part  = (float*)(smem + SM_PART);
    float* smean = (float*)(smem + SM_MEAN);
    float* srstd = (float*)(smem + SM_RSTD);
    const int mbase = mh * 32;

    // bias add (local cols)
#pragma unroll
    for (int nt = 0; nt < 8; nt++) {
        int c0 = wb + 8 * nt + 2 * q;
        float b0 = bs[c0], b1 = bs[c0 + 1];
#pragma unroll
        for (int mt = 0; mt < 2; mt++) {
            acc[mt][nt][0] += b0; acc[mt][nt][1] += b1;
            acc[mt][nt][2] += b0; acc[mt][nt][3] += b1;
        }
    }

    // per-row partial sums over this CTA's 256 cols
    float sA[2], qA[2], sB[2], qB[2];
#pragma unroll
    for (int mt = 0; mt < 2; mt++) {
        float s0 = 0.f, q0 = 0.f, s1 = 0.f, q1 = 0.f;
#pragma unroll
        for (int nt = 0; nt < 8; nt++) {
            float v0 = acc[mt][nt][0], v1 = acc[mt][nt][1];
            float v2 = acc[mt][nt][2], v3 = acc[mt][nt][3];
            s0 += v0 + v1;  q0 += v0 * v0 + v1 * v1;
            s1 += v2 + v3;  q1 += v2 * v2 + v3 * v3;
        }
        sA[mt] = s0; qA[mt] = q0; sB[mt] = s1; qB[mt] = q1;
    }
#pragma unroll
    for (int off = 1; off <= 2; off <<= 1) {
#pragma unroll
        for (int mt = 0; mt < 2; mt++) {
            sA[mt] += __shfl_xor_sync(0xffffffffu, sA[mt], off);
            qA[mt] += __shfl_xor_sync(0xffffffffu, qA[mt], off);
            sB[mt] += __shfl_xor_sync(0xffffffffu, sB[mt], off);
            qB[mt] += __shfl_xor_sync(0xffffffffu, qB[mt], off);
        }
    }
    if (q == 0) {
#pragma unroll
        for (int mt = 0; mt < 2; mt++) {
            int rA = mbase + 16 * mt + g;
            rsum[rA * 4 + nw]       = sA[mt];
            rsq [rA * 4 + nw]       = qA[mt];
            rsum[(rA + 8) * 4 + nw] = sB[mt];
            rsq [(rA + 8) * 4 + nw] = qB[mt];
        }
    }
    __syncthreads();

    float ls = 0.f, lq = 0.f;
    if (tid < 64) {
#pragma unroll
        for (int w = 0; w < 4; w++) { ls += rsum[tid * 4 + w]; lq += rsq[tid * 4 + w]; }
        part[tid * 2]     = ls;
        part[tid * 2 + 1] = lq;
    }

    // exchange partials with cluster peer via DSMEM
    CLUSTER_SYNC();
    if (tid < 64) {
        uint32_t pa = sb + SM_PART + (uint32_t)tid * 8;
        uint32_t ra;
        asm volatile("mapa.shared::cluster.u32 %0, %1, %2;" : "=r"(ra) : "r"(pa), "r"(peer));
        float rs, rq;
        asm volatile("ld.shared::cluster.v2.f32 {%0,%1}, [%2];" : "=f"(rs), "=f"(rq) : "r"(ra));
        float s  = ls + rs;
        float sq = lq + rq;
        float mean = s * (1.0f / 512.0f);
        float var  = sq * (1.0f / 512.0f) - mean * mean;
        smean[tid] = mean;
        srstd[tid] = rsqrtf(var + 1e-5f);
    }
    CLUSTER_SYNC();   // remote reads done; smean/srstd visible CTA-wide

    // normalize + LeakyReLU -> padded smem staging (reuses B region)
    const uint32_t OS = sb + SM_B;
#pragma unroll
    for (int mt = 0; mt < 2; mt++) {
        int rA = mbase + 16 * mt + g, rB = rA + 8;
        float mA = smean[rA], rsdA = srstd[rA];
        float mB = smean[rB], rsdB = srstd[rB];
#pragma unroll
        for (int nt = 0; nt < 8; nt++) {
            int c0 = wb + 8 * nt + 2 * q;
            float g0 = gs[c0], g1 = gs[c0 + 1];
            float e0 = es[c0], e1 = es[c0 + 1];
            float t0 = (acc[mt][nt][0] - mA) * rsdA * g0 + e0;
            float t1 = (acc[mt][nt][1] - mA) * rsdA * g1 + e1;
            float t2 = (acc[mt][nt][2] - mB) * rsdB * g0 + e0;
            float t3 = (acc[mt][nt][3] - mB) * rsdB * g1 + e1;
            t0 = fmaxf(t0, 0.2f * t0);
            t1 = fmaxf(t1, 0.2f * t1);
            t2 = fmaxf(t2, 0.2f * t2);
            t3 = fmaxf(t3, 0.2f * t3);
            uint32_t a0 = OS + (uint32_t)(rA * OUT_STRIDE_W + c0) * 4;
            uint32_t a1 = OS + (uint32_t)(rB * OUT_STRIDE_W + c0) * 4;
            asm volatile("st.shared.v2.f32 [%0], {%1, %2};" :: "r"(a0), "f"(t0), "f"(t1) : "memory");
            asm volatile("st.shared.v2.f32 [%0], {%1, %2};" :: "r"(a1), "f"(t2), "f"(t3) : "memory");
        }
    }
    __syncthreads();

    // coalesced writeback: 64 rows x 256 f32 = 4096 float4s
#pragma unroll
    for (int it = 0; it < 16; it++) {
        int id  = it * THREADS + tid;
        int row = id >> 6;          // 64 float4 per row
        int j   = id & 63;
        int gr  = m0 + row;
        if (gr < N_NODES) {
            uint32_t a = OS + (uint32_t)(row * OUT_STRIDE_W + j * 4) * 4;
            uint32_t v0, v1, v2, v3;
            asm volatile("ld.shared.v4.b32 {%0, %1, %2, %3}, [%4];"
                         : "=r"(v0), "=r"(v1), "=r"(v2), "=r"(v3) : "r"(a));
            float4 o;
            o.x = __uint_as_float(v0); o.y = __uint_as_float(v1);
            o.z = __uint_as_float(v2); o.w = __uint_as_float(v3);
            *(float4*)(out + (size_t)gr * DIM + ncol0 + j * 4) = o;
        }
    }
}

extern "C" void kernel_launch(void* const* d_in, const int* in_sizes, int n_in,
                              void* d_out, int out_size) {
    const float* x     = (const float*)d_in[0];
    // d_in[1] edge_attr, d_in[2] edge_index, d_in[3] batch: dead inputs
    const float* W     = (const float*)d_in[4];
    const float* bias  = (const float*)d_in[5];
    const float* gamma = (const float*)d_in[6];
    const float* beta  = (const float*)d_in[7];
    float* out = (float*)d_out;

    wconv_kernel<<<256, 256>>>(W);

    cudaFuncSetAttribute(fused_gemm_ln_lrelu,
                         cudaFuncAttributeMaxDynamicSharedMemorySize, SMEM_TOTAL);
    fused_gemm_ln_lrelu<<<GRID, THREADS, SMEM_TOTAL>>>(x, bias, gamma, beta, out);
}

// round 10
// speedup vs baseline: 1.3204x; 1.3204x over previous
#include <cuda_runtime.h>
#include <cuda_fp16.h>
#include <cstdint>

#define N_NODES   100000
#define DIM       512
#define TILE_M    64
#define KCH       64                 // K halfs per chunk (128B per row)
#define N_CHUNKS  8
#define THREADS   512
#define NUM_TILES ((N_NODES + TILE_M - 1) / TILE_M)   // 1563

// XOR-swizzled rows: 128B, granule g at (g ^ (row&7))*16
#define A_STAGE   8192               // 64 rows x 128B
#define B_STAGE   65536              // 512 rows x 128B

#define SM_BIAS   0
#define SM_GAMMA  2048
#define SM_BETA   4096
#define SM_RSUM   6144               // [64][8] f32
#define SM_RSQ    8192               // [64][8] f32
#define SM_MEAN   10240
#define SM_RSTD   10496
#define SM_MBAR   10752              // 10 mbarriers x 8B
#define SM_A      11264              // 2 stages
#define SM_B      27648              // 3 stages
#define SMEM_TOTAL (SM_B + 3 * B_STAGE)   // 224256

#define OUT_STRIDE_W 520             // epilogue staging stride (words)

__device__ __half g_Wh[512 * 512];   // pre-converted W (512KB, L2-resident)

static __device__ __forceinline__ uint32_t smem_u32(const void* p) {
    uint32_t a;
    asm("{ .reg .u64 t; cvta.to.shared.u64 t, %1; cvt.u32.u64 %0, t; }" : "=r"(a) : "l"(p));
    return a;
}

#define LDSM4(r, a) \
    asm volatile("ldmatrix.sync.aligned.m8n8.x4.shared.b16 {%0,%1,%2,%3}, [%4];" \
        : "=r"((r)[0]), "=r"((r)[1]), "=r"((r)[2]), "=r"((r)[3]) : "r"(a))

static __device__ __forceinline__ void mma_f16(float* d, const uint32_t* a,
                                               uint32_t b0, uint32_t b1) {
    asm volatile(
        "mma.sync.aligned.m16n8k16.row.col.f32.f16.f16.f32 "
        "{%0,%1,%2,%3}, {%4,%5,%6,%7}, {%8,%9}, {%0,%1,%2,%3};"
        : "+f"(d[0]), "+f"(d[1]), "+f"(d[2]), "+f"(d[3])
        : "r"(a[0]), "r"(a[1]), "r"(a[2]), "r"(a[3]), "r"(b0), "r"(b1));
}

static __device__ __forceinline__ void cp16(uint32_t dst, const void* src) {
    asm volatile("cp.async.cg.shared.global [%0], [%1], 16;" :: "r"(dst), "l"(src));
}

#define MBAR_INIT(addr, cnt) \
    asm volatile("mbarrier.init.shared.b64 [%0], %1;" :: "r"(addr), "r"(cnt) : "memory")

#define MBAR_ARRIVE(addr) \
    asm volatile("mbarrier.arrive.shared.b64 _, [%0];" :: "r"(addr) : "memory")

// .noinc: the completion-arrive COUNTS toward the expected arrival count.
// (default form pre-increments pending count -> net zero -> deadlock, R9 bug)
#define CPASYNC_MBAR_ARRIVE(addr) \
    asm volatile("cp.async.mbarrier.arrive.noinc.shared.b64 [%0];" :: "r"(addr) : "memory")

#define MBAR_WAIT(addr, parity) do {                                              \
    uint32_t _m = (addr); uint32_t _p = (uint32_t)(parity); uint32_t _d;          \
    asm volatile("{\n\t.reg .pred p;\n\t"                                         \
        "mbarrier.try_wait.parity.acquire.cta.shared::cta.b64 p, [%1], %2;\n\t"   \
        "selp.b32 %0, 1, 0, p;\n\t}" : "=r"(_d) : "r"(_m), "r"(_p) : "memory");   \
    if (!_d) {                                                                    \
        asm volatile("{\n\t.reg .pred P1;\n\t"                                    \
        "W_%=:\n\t"                                                               \
        "mbarrier.try_wait.parity.acquire.cta.shared::cta.b64 P1, [%0], %1, 0x989680;\n\t" \
        "@P1 bra.uni D_%=;\n\t"                                                   \
        "bra.uni W_%=;\n\t"                                                       \
        "D_%=:\n\t}" :: "r"(_m), "r"(_p) : "memory");                             \
    }                                                                             \
} while (0)

// barrier addresses: [0..2] full_b, [3..5] empty_b, [6..7] full_a, [8..9] empty_a
#define FULL_B(s)  (mb + (uint32_t)(s) * 8u)
#define EMPTY_B(s) (mb + 24u + (uint32_t)(s) * 8u)
#define FULL_A(s)  (mb + 48u + (uint32_t)(s) * 8u)
#define EMPTY_A(s) (mb + 64u + (uint32_t)(s) * 8u)

// B chunk: 512 rows x 128B fp16 from g_Wh, XOR-swizzled
static __device__ __forceinline__ void load_B(int kc, uint32_t b_base, int tid) {
#pragma unroll
    for (int it = 0; it < 8; it++) {
        int id  = it * THREADS + tid;
        int row = id >> 3, j = id & 7;
        cp16(b_base + (uint32_t)(row * 128 + ((j ^ (row & 7)) << 4)),
             g_Wh + (size_t)row * DIM + kc * KCH + j * 8);
    }
}

// A chunk LDG: thread -> row tid>>3, 8 f32 at col (tid&7)*8
static __device__ __forceinline__ void ldg_A(const float* __restrict__ x,
                                             int m0, int kc, int tid, float4* r) {
    int row = tid >> 3;
    int gr  = m0 + row;
    if (gr > N_NODES - 1) gr = N_NODES - 1;   // clamped rows never stored
    const float* p = x + (size_t)gr * DIM + kc * KCH + (tid & 7) * 8;
    r[0] = *(const float4*)(p);
    r[1] = *(const float4*)(p + 4);
}

// convert + store A chunk (8 f32 -> 8 halfs = 1 granule), XOR-swizzled
static __device__ __forceinline__ void sts_A(uint32_t a_base, int tid, const float4* r) {
    int row = tid >> 3, j = tid & 7;
    uint32_t a = a_base + (uint32_t)(row * 128 + ((j ^ (row & 7)) << 4));
    __half2 x0 = __floats2half2_rn(r[0].x, r[0].y);
    __half2 x1 = __floats2half2_rn(r[0].z, r[0].w);
    __half2 x2 = __floats2half2_rn(r[1].x, r[1].y);
    __half2 x3 = __floats2half2_rn(r[1].z, r[1].w);
    asm volatile("st.shared.v4.b32 [%0], {%1,%2,%3,%4};" :: "r"(a),
                 "r"(*(uint32_t*)&x0), "r"(*(uint32_t*)&x1),
                 "r"(*(uint32_t*)&x2), "r"(*(uint32_t*)&x3) : "memory");
}

__global__ void wconv_kernel(const float* __restrict__ W) {
    int i = (blockIdx.x * blockDim.x + threadIdx.x) * 4;
    float4 v = *(const float4*)(W + i);
    __half2 h0 = __floats2half2_rn(v.x, v.y);
    __half2 h1 = __floats2half2_rn(v.z, v.w);
    *(__half2*)(g_Wh + i)     = h0;
    *(__half2*)(g_Wh + i + 2) = h1;
}

__global__ void __launch_bounds__(THREADS, 1)
fused_gemm_ln_lrelu(const float* __restrict__ x,
                    const float* __restrict__ bias, const float* __restrict__ gamma,
                    const float* __restrict__ beta, float* __restrict__ out) {
    extern __shared__ __align__(1024) char smem[];
    const uint32_t sb = smem_u32(smem);
    const uint32_t mb = sb + SM_MBAR;
    const int tid  = threadIdx.x;
    const int lane = tid & 31;
    const int wid  = tid >> 5;          // 0..15
    const int q    = lane & 3;
    const int g    = lane >> 2;
    const int mh   = wid >> 3;          // M half: rows [32*mh, +32)
    const int nw   = wid & 7;           // N slice: cols [64*nw, +64)
    const int m0   = blockIdx.x * TILE_M;

    ((float*)(smem + SM_BIAS))[tid]  = bias[tid];
    ((float*)(smem + SM_GAMMA))[tid] = gamma[tid];
    ((float*)(smem + SM_BETA))[tid]  = beta[tid];
    if (tid < 10) MBAR_INIT(mb + (uint32_t)tid * 8u, THREADS);
    __syncthreads();   // mbarriers + params visible

    float acc[2][8][4];
#pragma unroll
    for (int mt = 0; mt < 2; mt++)
#pragma unroll
        for (int nt = 0; nt < 8; nt++)
#pragma unroll
            for (int u = 0; u < 4; u++) acc[mt][nt][u] = 0.f;

    // -------- per-lane ldmatrix address components --------
    const int mr0 = mh * 32 + (lane & 15);        // mt=0 row
    const int mr1 = mr0 + 16;                     // mt=1 row
    const int agsel = lane >> 4;                  // 0/1 (k-low/high granule)
    const uint32_t aoff0 = (uint32_t)(mr0 * 128);
    const uint32_t aoff1 = (uint32_t)(mr1 * 128);
    const int m7_0 = mr0 & 7, m7_1 = mr1 & 7;
    const int wb = nw * 64;
    int n7[4];
    uint32_t boff[4];
    const int bgsel = (lane >> 3) & 1;
#pragma unroll
    for (int p = 0; p < 4; p++) {
        int nr = wb + p * 16 + (lane & 7) + ((lane >> 4) << 3);
        n7[p] = nr & 7;
        boff[p] = (uint32_t)(nr * 128);
    }

    const uint32_t ab = sb + SM_A;
    const uint32_t bb = sb + SM_B;

    // -------- prologue: chunk0 A+B, chunk1 B; A(1) kept in regs --------
    float4 r[2];
    ldg_A(x, m0, 0, tid, r);
    load_B(0, bb, tid);
    CPASYNC_MBAR_ARRIVE(FULL_B(0));
    sts_A(ab, tid, r);
    MBAR_ARRIVE(FULL_A(0));
    ldg_A(x, m0, 1, tid, r);
    load_B(1, bb + B_STAGE, tid);
    CPASYNC_MBAR_ARRIVE(FULL_B(1));

#pragma unroll 1
    for (int i = 0; i < N_CHUNKS; i++) {
        // ---- producer: B(i+2) and A(i+1) into their ring slots ----
        if (i + 2 < N_CHUNKS) {
            const int s = (i + 2) % 3, u = (i + 2) / 3;
            if (u >= 1) MBAR_WAIT(EMPTY_B(s), (u - 1) & 1);
            load_B(i + 2, bb + (uint32_t)s * B_STAGE, tid);
            CPASYNC_MBAR_ARRIVE(FULL_B(s));
        }
        if (i + 1 < N_CHUNKS) {
            const int s = (i + 1) & 1, u = (i + 1) >> 1;
            if (u >= 1) MBAR_WAIT(EMPTY_A(s), (u - 1) & 1);
            sts_A(ab + (uint32_t)s * A_STAGE, tid, r);
            MBAR_ARRIVE(FULL_A(s));
            if (i + 2 < N_CHUNKS) ldg_A(x, m0, i + 2, tid, r);
        }

        // ---- consumer: wait chunk i full ----
        const int bs = i % 3, as = i & 1;
        MBAR_WAIT(FULL_B(bs), (i / 3) & 1);
        MBAR_WAIT(FULL_A(as), (i >> 1) & 1);

        const uint32_t SA  = ab + (uint32_t)as * A_STAGE;
        const uint32_t SBs = bb + (uint32_t)bs * B_STAGE;

        // prime fragment pipeline
        uint32_t af[2][2][4], bf[2][4];
        LDSM4(af[0][0], SA + aoff0 + (uint32_t)((agsel ^ m7_0) << 4));
        LDSM4(af[0][1], SA + aoff1 + (uint32_t)((agsel ^ m7_1) << 4));
        LDSM4(bf[0],    SBs + boff[0] + (uint32_t)((bgsel ^ n7[0]) << 4));

        // -------- 16-step (ks,p) pipeline: 1 B-LDSM + 4 MMA per step --------
#pragma unroll
        for (int s = 0; s < 16; s++) {
            const int ks = s >> 2, p = s & 3;
            const int cur = s & 1, nxt = cur ^ 1;
            if (s < 15) {
                const int s1 = s + 1, ks1 = s1 >> 2, p1 = s1 & 3;
                LDSM4(bf[nxt], SBs + boff[p1] +
                      (uint32_t)(((2 * ks1 + bgsel) ^ n7[p1]) << 4));
            }
            if (p == 0 && ks < 3) {
                const int c2 = 2 * (ks + 1), nb = (ks + 1) & 1;
                LDSM4(af[nb][0], SA + aoff0 + (uint32_t)(((c2 + agsel) ^ m7_0) << 4));
                LDSM4(af[nb][1], SA + aoff1 + (uint32_t)(((c2 + agsel) ^ m7_1) << 4));
            }
            const int abuf = ks & 1;
            mma_f16(acc[0][2 * p],     af[abuf][0], bf[cur][0], bf[cur][1]);
            mma_f16(acc[0][2 * p + 1], af[abuf][0], bf[cur][2], bf[cur][3]);
            mma_f16(acc[1][2 * p],     af[abuf][1], bf[cur][0], bf[cur][1]);
            mma_f16(acc[1][2 * p + 1], af[abuf][1], bf[cur][2], bf[cur][3]);
        }

        // ---- release chunk i stages ----
        MBAR_ARRIVE(EMPTY_B(bs));
        MBAR_ARRIVE(EMPTY_A(as));
    }

    // ---------------- epilogue ----------------
    const float* bs_ = (const float*)(smem + SM_BIAS);
    const float* gs = (const float*)(smem + SM_GAMMA);
    const float* es = (const float*)(smem + SM_BETA);
    float* rsum  = (float*)(smem + SM_RSUM);
    float* rsq   = (float*)(smem + SM_RSQ);
    float* smean = (float*)(smem + SM_MEAN);
    float* srstd = (float*)(smem + SM_RSTD);
    const int mbase = mh * 32;

#pragma unroll
    for (int nt = 0; nt < 8; nt++) {
        int c0 = wb + 8 * nt + 2 * q;
        float b0 = bs_[c0], b1 = bs_[c0 + 1];
#pragma unroll
        for (int mt = 0; mt < 2; mt++) {
            acc[mt][nt][0] += b0; acc[mt][nt][1] += b1;
            acc[mt][nt][2] += b0; acc[mt][nt][3] += b1;
        }
    }

    float sA[2], qA[2], sB[2], qB[2];
#pragma unroll
    for (int mt = 0; mt < 2; mt++) {
        float s0 = 0.f, q0 = 0.f, s1 = 0.f, q1 = 0.f;
#pragma unroll
        for (int nt = 0; nt < 8; nt++) {
            float v0 = acc[mt][nt][0], v1 = acc[mt][nt][1];
            float v2 = acc[mt][nt][2], v3 = acc[mt][nt][3];
            s0 += v0 + v1;  q0 += v0 * v0 + v1 * v1;
            s1 += v2 + v3;  q1 += v2 * v2 + v3 * v3;
        }
        sA[mt] = s0; qA[mt] = q0; sB[mt] = s1; qB[mt] = q1;
    }
#pragma unroll
    for (int off = 1; off <= 2; off <<= 1) {
#pragma unroll
        for (int mt = 0; mt < 2; mt++) {
            sA[mt] += __shfl_xor_sync(0xffffffffu, sA[mt], off);
            qA[mt] += __shfl_xor_sync(0xffffffffu, qA[mt], off);
            sB[mt] += __shfl_xor_sync(0xffffffffu, sB[mt], off);
            qB[mt] += __shfl_xor_sync(0xffffffffu, qB[mt], off);
        }
    }
    if (q == 0) {
#pragma unroll
        for (int mt = 0; mt < 2; mt++) {
            int rA = mbase + 16 * mt + g;
            rsum[rA * 8 + nw]       = sA[mt];
            rsq [rA * 8 + nw]       = qA[mt];
            rsum[(rA + 8) * 8 + nw] = sB[mt];
            rsq [(rA + 8) * 8 + nw] = qB[mt];
        }
    }
    __syncthreads();

    if (tid < 64) {
        float s = 0.f, ss = 0.f;
#pragma unroll
        for (int w = 0; w < 8; w++) { s += rsum[tid * 8 + w]; ss += rsq[tid * 8 + w]; }
        float mean = s * (1.0f / 512.0f);
        float var  = ss * (1.0f / 512.0f) - mean * mean;
        smean[tid] = mean;
        srstd[tid] = rsqrtf(var + 1e-5f);
    }
    __syncthreads();

    const uint32_t OS = sb + SM_B;   // staging reuses B region (all warps past mainloop)
#pragma unroll
    for (int mt = 0; mt < 2; mt++) {
        int rA = mbase + 16 * mt + g, rB = rA + 8;
        float mA = smean[rA], rsdA = srstd[rA];
        float mB = smean[rB], rsdB = srstd[rB];
#pragma unroll
        for (int nt = 0; nt < 8; nt++) {
            int c0 = wb + 8 * nt + 2 * q;
            float g0 = gs[c0], g1 = gs[c0 + 1];
            float e0 = es[c0], e1 = es[c0 + 1];
            float t0 = (acc[mt][nt][0] - mA) * rsdA * g0 + e0;
            float t1 = (acc[mt][nt][1] - mA) * rsdA * g1 + e1;
            float t2 = (acc[mt][nt][2] - mB) * rsdB * g0 + e0;
            float t3 = (acc[mt][nt][3] - mB) * rsdB * g1 + e1;
            t0 = fmaxf(t0, 0.2f * t0);
            t1 = fmaxf(t1, 0.2f * t1);
            t2 = fmaxf(t2, 0.2f * t2);
            t3 = fmaxf(t3, 0.2f * t3);
            uint32_t a0 = OS + (uint32_t)(rA * OUT_STRIDE_W + c0) * 4;
            uint32_t a1 = OS + (uint32_t)(rB * OUT_STRIDE_W + c0) * 4;
            asm volatile("st.shared.v2.f32 [%0], {%1, %2};" :: "r"(a0), "f"(t0), "f"(t1) : "memory");
            asm volatile("st.shared.v2.f32 [%0], {%1, %2};" :: "r"(a1), "f"(t2), "f"(t3) : "memory");
        }
    }
    __syncthreads();

    // coalesced writeback: 64 rows x 512 f32 = 8192 float4s
#pragma unroll
    for (int it = 0; it < 16; it++) {
        int id  = it * THREADS + tid;
        int row = id >> 7;
        int j   = id & 127;
        int gr  = m0 + row;
        if (gr < N_NODES) {
            uint32_t a = OS + (uint32_t)(row * OUT_STRIDE_W + j * 4) * 4;
            uint32_t v0, v1, v2, v3;
            asm volatile("ld.shared.v4.b32 {%0, %1, %2, %3}, [%4];"
                         : "=r"(v0), "=r"(v1), "=r"(v2), "=r"(v3) : "r"(a));
            float4 o;
            o.x = __uint_as_float(v0); o.y = __uint_as_float(v1);
            o.z = __uint_as_float(v2); o.w = __uint_as_float(v3);
            *(float4*)(out + (size_t)gr * DIM + j * 4) = o;
        }
    }
}

extern "C" void kernel_launch(void* const* d_in, const int* in_sizes, int n_in,
                              void* d_out, int out_size) {
    const float* x     = (const float*)d_in[0];
    // d_in[1] edge_attr, d_in[2] edge_index, d_in[3] batch: dead inputs
    const float* W     = (const float*)d_in[4];
    const float* bias  = (const float*)d_in[5];
    const float* gamma = (const float*)d_in[6];
    const float* beta  = (const float*)d_in[7];
    float* out = (float*)d_out;

    wconv_kernel<<<256, 256>>>(W);

    cudaFuncSetAttribute(fused_gemm_ln_lrelu,
                         cudaFuncAttributeMaxDynamicSharedMemorySize, SMEM_TOTAL);
    fused_gemm_ln_lrelu<<<NUM_TILES, THREADS, SMEM_TOTAL>>>(x, bias, gamma, beta, out);
}

// round 11
// speedup vs baseline: 1.3520x; 1.0239x over previous
#include <cuda_runtime.h>
#include <cuda_fp16.h>
#include <cstdint>

#define N_NODES   100000
#define DIM       512
#define TILE_M    64
#define KCH       64                 // K halfs per chunk (128B per row)
#define N_CHUNKS  8
#define THREADS   512
#define NUM_TILES ((N_NODES + TILE_M - 1) / TILE_M)   // 1563

// XOR-swizzled rows: 128B, granule g at (g ^ (row&7))*16
#define A_STAGE   8192               // 64 rows x 128B
#define B_STAGE   65536              // 512 rows x 128B

#define SM_BIAS   0
#define SM_GAMMA  2048
#define SM_BETA   4096
#define SM_RSUM   6144               // [64][8] f32
#define SM_RSQ    8192               // [64][8] f32
#define SM_MEAN   10240
#define SM_RSTD   10496
#define SM_A      11264              // 2 stages
#define SM_B      27648              // 3 stages
#define SMEM_TOTAL (SM_B + 3 * B_STAGE)   // 224256

__device__ __half g_Wh[512 * 512];   // pre-converted W (512KB, L2-resident)

static __device__ __forceinline__ uint32_t smem_u32(const void* p) {
    uint32_t a;
    asm("{ .reg .u64 t; cvta.to.shared.u64 t, %1; cvt.u32.u64 %0, t; }" : "=r"(a) : "l"(p));
    return a;
}

#define LDSM4(r, a) \
    asm volatile("ldmatrix.sync.aligned.m8n8.x4.shared.b16 {%0,%1,%2,%3}, [%4];" \
        : "=r"((r)[0]), "=r"((r)[1]), "=r"((r)[2]), "=r"((r)[3]) : "r"(a))

static __device__ __forceinline__ void mma_f16(float* d, const uint32_t* a,
                                               uint32_t b0, uint32_t b1) {
    asm volatile(
        "mma.sync.aligned.m16n8k16.row.col.f32.f16.f16.f32 "
        "{%0,%1,%2,%3}, {%4,%5,%6,%7}, {%8,%9}, {%0,%1,%2,%3};"
        : "+f"(d[0]), "+f"(d[1]), "+f"(d[2]), "+f"(d[3])
        : "r"(a[0]), "r"(a[1]), "r"(a[2]), "r"(a[3]), "r"(b0), "r"(b1));
}

static __device__ __forceinline__ void cp16(uint32_t dst, const void* src) {
    asm volatile("cp.async.cg.shared.global [%0], [%1], 16;" :: "r"(dst), "l"(src));
}

// B chunk: 512 rows x 128B fp16 from g_Wh, XOR-swizzled
static __device__ __forceinline__ void load_B(int kc, uint32_t b_base, int tid) {
#pragma unroll
    for (int it = 0; it < 8; it++) {
        int id  = it * THREADS + tid;
        int row = id >> 3, j = id & 7;
        cp16(b_base + (uint32_t)(row * 128 + ((j ^ (row & 7)) << 4)),
             g_Wh + (size_t)row * DIM + kc * KCH + j * 8);
    }
}

// A chunk LDG: thread -> row tid>>3, 8 f32 at col (tid&7)*8
static __device__ __forceinline__ void ldg_A(const float* __restrict__ x,
                                             int m0, int kc, int tid, float4* r) {
    int row = tid >> 3;
    int gr  = m0 + row;
    if (gr > N_NODES - 1) gr = N_NODES - 1;   // clamped rows never stored
    const float* p = x + (size_t)gr * DIM + kc * KCH + (tid & 7) * 8;
    r[0] = *(const float4*)(p);
    r[1] = *(const float4*)(p + 4);
}

// convert + store A chunk (8 f32 -> 8 halfs = 1 granule), XOR-swizzled
static __device__ __forceinline__ void sts_A(uint32_t a_base, int tid, const float4* r) {
    int row = tid >> 3, j = tid & 7;
    uint32_t a = a_base + (uint32_t)(row * 128 + ((j ^ (row & 7)) << 4));
    __half2 x0 = __floats2half2_rn(r[0].x, r[0].y);
    __half2 x1 = __floats2half2_rn(r[0].z, r[0].w);
    __half2 x2 = __floats2half2_rn(r[1].x, r[1].y);
    __half2 x3 = __floats2half2_rn(r[1].z, r[1].w);
    asm volatile("st.shared.v4.b32 [%0], {%1,%2,%3,%4};" :: "r"(a),
                 "r"(*(uint32_t*)&x0), "r"(*(uint32_t*)&x1),
                 "r"(*(uint32_t*)&x2), "r"(*(uint32_t*)&x3) : "memory");
}

__global__ void wconv_kernel(const float* __restrict__ W) {
    int i = (blockIdx.x * blockDim.x + threadIdx.x) * 4;
    float4 v = *(const float4*)(W + i);
    __half2 h0 = __floats2half2_rn(v.x, v.y);
    __half2 h1 = __floats2half2_rn(v.z, v.w);
    *(__half2*)(g_Wh + i)     = h0;
    *(__half2*)(g_Wh + i + 2) = h1;
}

__global__ void __launch_bounds__(THREADS, 1)
fused_gemm_ln_lrelu(const float* __restrict__ x,
                    const float* __restrict__ bias, const float* __restrict__ gamma,
                    const float* __restrict__ beta, float* __restrict__ out) {
    extern __shared__ __align__(1024) char smem[];
    const uint32_t sb = smem_u32(smem);
    const int tid  = threadIdx.x;
    const int lane = tid & 31;
    const int wid  = tid >> 5;          // 0..15
    const int q    = lane & 3;
    const int g    = lane >> 2;
    const int mh   = wid >> 3;          // M half: rows [32*mh, +32)
    const int nw   = wid & 7;           // N slice: cols [64*nw, +64)
    const int m0   = blockIdx.x * TILE_M;

    ((float*)(smem + SM_BIAS))[tid]  = bias[tid];
    ((float*)(smem + SM_GAMMA))[tid] = gamma[tid];
    ((float*)(smem + SM_BETA))[tid]  = beta[tid];

    float acc[2][8][4];
#pragma unroll
    for (int mt = 0; mt < 2; mt++)
#pragma unroll
        for (int nt = 0; nt < 8; nt++)
#pragma unroll
            for (int u = 0; u < 4; u++) acc[mt][nt][u] = 0.f;

    // -------- per-lane ldmatrix address components --------
    const int mr0 = mh * 32 + (lane & 15);        // mt=0 row
    const int mr1 = mr0 + 16;                     // mt=1 row
    const int agsel = lane >> 4;                  // 0/1 (k-low/high granule)
    const uint32_t aoff0 = (uint32_t)(mr0 * 128);
    const uint32_t aoff1 = (uint32_t)(mr1 * 128);
    const int m7_0 = mr0 & 7, m7_1 = mr1 & 7;
    const int wb = nw * 64;
    int n7[4];
    uint32_t boff[4];
    const int bgsel = (lane >> 3) & 1;
#pragma unroll
    for (int p = 0; p < 4; p++) {
        int nr = wb + p * 16 + (lane & 7) + ((lane >> 4) << 3);
        n7[p] = nr & 7;
        boff[p] = (uint32_t)(nr * 128);
    }

    const uint32_t ab = sb + SM_A;
    const uint32_t bb = sb + SM_B;

    // -------- prologue --------
    float4 r[2];
    ldg_A(x, m0, 0, tid, r);
    load_B(0, bb, tid);
    asm volatile("cp.async.commit_group;" ::: "memory");
    sts_A(ab, tid, r);
    ldg_A(x, m0, 1, tid, r);
    load_B(1, bb + B_STAGE, tid);
    asm volatile("cp.async.commit_group;" ::: "memory");

    int bidx = 0;   // B stage of current chunk

#pragma unroll 1
    for (int i = 0; i < N_CHUNKS; i++) {
        if (i < N_CHUNKS - 1) asm volatile("cp.async.wait_group 1;" ::: "memory");
        else                  asm volatile("cp.async.wait_group 0;" ::: "memory");
        __syncthreads();   // B(i),A(i) visible; stages for (i+2)/(i+1) drained

        const uint32_t SA  = ab + (uint32_t)(i & 1) * A_STAGE;
        const uint32_t SBs = bb + (uint32_t)bidx * B_STAGE;

        // prime fragment pipeline (fill latency hides behind cp.async issue below)
        uint32_t af[2][2][4], bf[2][4];
        LDSM4(af[0][0], SA + aoff0 + (uint32_t)((agsel ^ m7_0) << 4));
        LDSM4(af[0][1], SA + aoff1 + (uint32_t)((agsel ^ m7_1) << 4));
        LDSM4(bf[0],    SBs + boff[0] + (uint32_t)((bgsel ^ n7[0]) << 4));

        // issue next loads into drained stages
        if (i + 2 < N_CHUNKS) {
            int b2 = bidx + 2; if (b2 >= 3) b2 -= 3;
            load_B(i + 2, bb + (uint32_t)b2 * B_STAGE, tid);
            asm volatile("cp.async.commit_group;" ::: "memory");
        }
        if (i + 1 < N_CHUNKS) {
            sts_A(ab + (uint32_t)((i + 1) & 1) * A_STAGE, tid, r);
            if (i + 2 < N_CHUNKS) ldg_A(x, m0, i + 2, tid, r);
        }

        // -------- 16-step (ks,p) pipeline: 1 B-LDSM + 4 MMA per step --------
#pragma unroll
        for (int s = 0; s < 16; s++) {
            const int ks = s >> 2, p = s & 3;
            const int cur = s & 1, nxt = cur ^ 1;
            if (s < 15) {
                const int s1 = s + 1, ks1 = s1 >> 2, p1 = s1 & 3;
                LDSM4(bf[nxt], SBs + boff[p1] +
                      (uint32_t)(((2 * ks1 + bgsel) ^ n7[p1]) << 4));
            }
            if (p == 0 && ks < 3) {
                const int c2 = 2 * (ks + 1), nb = (ks + 1) & 1;
                LDSM4(af[nb][0], SA + aoff0 + (uint32_t)(((c2 + agsel) ^ m7_0) << 4));
                LDSM4(af[nb][1], SA + aoff1 + (uint32_t)(((c2 + agsel) ^ m7_1) << 4));
            }
            const int abuf = ks & 1;
            mma_f16(acc[0][2 * p],     af[abuf][0], bf[cur][0], bf[cur][1]);
            mma_f16(acc[0][2 * p + 1], af[abuf][0], bf[cur][2], bf[cur][3]);
            mma_f16(acc[1][2 * p],     af[abuf][1], bf[cur][0], bf[cur][1]);
            mma_f16(acc[1][2 * p + 1], af[abuf][1], bf[cur][2], bf[cur][3]);
        }

        __syncthreads();   // all warps done reading stage SA

        if (++bidx == 3) bidx = 0;
    }

    // ---------------- epilogue ----------------
    const float* bs = (const float*)(smem + SM_BIAS);
    const float* gs = (const float*)(smem + SM_GAMMA);
    const float* es = (const float*)(smem + SM_BETA);
    float* rsum  = (float*)(smem + SM_RSUM);
    float* rsq   = (float*)(smem + SM_RSQ);
    float* smean = (float*)(smem + SM_MEAN);
    float* srstd = (float*)(smem + SM_RSTD);
    const int mbase = mh * 32;

    // bias add (in-register)
#pragma unroll
    for (int nt = 0; nt < 8; nt++) {
        int c0 = wb + 8 * nt + 2 * q;
        float b0 = bs[c0], b1 = bs[c0 + 1];
#pragma unroll
        for (int mt = 0; mt < 2; mt++) {
            acc[mt][nt][0] += b0; acc[mt][nt][1] += b1;
            acc[mt][nt][2] += b0; acc[mt][nt][3] += b1;
        }
    }

    // per-row partial sums (rows mbase+16mt+g and +8)
    float sA[2], qA[2], sB[2], qB[2];
#pragma unroll
    for (int mt = 0; mt < 2; mt++) {
        float s0 = 0.f, q0 = 0.f, s1 = 0.f, q1 = 0.f;
#pragma unroll
        for (int nt = 0; nt < 8; nt++) {
            float v0 = acc[mt][nt][0], v1 = acc[mt][nt][1];
            float v2 = acc[mt][nt][2], v3 = acc[mt][nt][3];
            s0 += v0 + v1;  q0 += v0 * v0 + v1 * v1;
            s1 += v2 + v3;  q1 += v2 * v2 + v3 * v3;
        }
        sA[mt] = s0; qA[mt] = q0; sB[mt] = s1; qB[mt] = q1;
    }
#pragma unroll
    for (int off = 1; off <= 2; off <<= 1) {
#pragma unroll
        for (int mt = 0; mt < 2; mt++) {
            sA[mt] += __shfl_xor_sync(0xffffffffu, sA[mt], off);
            qA[mt] += __shfl_xor_sync(0xffffffffu, qA[mt], off);
            sB[mt] += __shfl_xor_sync(0xffffffffu, sB[mt], off);
            qB[mt] += __shfl_xor_sync(0xffffffffu, qB[mt], off);
        }
    }
    if (q == 0) {
#pragma unroll
        for (int mt = 0; mt < 2; mt++) {
            int rA = mbase + 16 * mt + g;
            rsum[rA * 8 + nw]       = sA[mt];
            rsq [rA * 8 + nw]       = qA[mt];
            rsum[(rA + 8) * 8 + nw] = sB[mt];
            rsq [(rA + 8) * 8 + nw] = qB[mt];
        }
    }
    __syncthreads();

    if (tid < 64) {
        float s = 0.f, ss = 0.f;
#pragma unroll
        for (int w = 0; w < 8; w++) { s += rsum[tid * 8 + w]; ss += rsq[tid * 8 + w]; }
        float mean = s * (1.0f / 512.0f);
        float var  = ss * (1.0f / 512.0f) - mean * mean;
        smean[tid] = mean;
        srstd[tid] = rsqrtf(var + 1e-5f);
    }
    __syncthreads();

    // normalize + LeakyReLU + shuffle-pack -> direct STG.128 (no smem staging)
    const int qeven = !(q & 1);
#pragma unroll
    for (int mt = 0; mt < 2; mt++) {
        int rA = mbase + 16 * mt + g, rB = rA + 8;
        float mA = smean[rA], rsdA = srstd[rA];
        float mB = smean[rB], rsdB = srstd[rB];
#pragma unroll
        for (int nt = 0; nt < 8; nt++) {
            int c0 = wb + 8 * nt + 2 * q;
            float g0 = gs[c0], g1 = gs[c0 + 1];
            float e0 = es[c0], e1 = es[c0 + 1];
            float t0 = (acc[mt][nt][0] - mA) * rsdA * g0 + e0;
            float t1 = (acc[mt][nt][1] - mA) * rsdA * g1 + e1;
            float t2 = (acc[mt][nt][2] - mB) * rsdB * g0 + e0;
            float t3 = (acc[mt][nt][3] - mB) * rsdB * g1 + e1;
            t0 = fmaxf(t0, 0.2f * t0);
            t1 = fmaxf(t1, 0.2f * t1);
            t2 = fmaxf(t2, 0.2f * t2);
            t3 = fmaxf(t3, 0.2f * t3);
            // pair lanes (q, q^1): even lane -> rowA 4 cols; odd -> rowB 4 cols
            float u0 = __shfl_xor_sync(0xffffffffu, t0, 1);
            float u1 = __shfl_xor_sync(0xffffffffu, t1, 1);
            float w2 = __shfl_xor_sync(0xffffffffu, t2, 1);
            float w3 = __shfl_xor_sync(0xffffffffu, t3, 1);
            float4 o;
            int grow, gcol;
            if (qeven) {
                o.x = t0; o.y = t1; o.z = u0; o.w = u1;
                grow = m0 + rA; gcol = c0;           // 2q even -> 16B aligned
            } else {
                o.x = w2; o.y = w3; o.z = t2; o.w = t3;
                grow = m0 + rB; gcol = c0 - 2;       // 2(q-1) -> 16B aligned
            }
            if (grow < N_NODES)
                *(float4*)(out + (size_t)grow * DIM + gcol) = o;
        }
    }
}

extern "C" void kernel_launch(void* const* d_in, const int* in_sizes, int n_in,
                              void* d_out, int out_size) {
    const float* x     = (const float*)d_in[0];
    // d_in[1] edge_attr, d_in[2] edge_index, d_in[3] batch: dead inputs
    const float* W     = (const float*)d_in[4];
    const float* bias  = (const float*)d_in[5];
    const float* gamma = (const float*)d_in[6];
    const float* beta  = (const float*)d_in[7];
    float* out = (float*)d_out;

    wconv_kernel<<<256, 256>>>(W);

    cudaFuncSetAttribute(fused_gemm_ln_lrelu,
                         cudaFuncAttributeMaxDynamicSharedMemorySize, SMEM_TOTAL);
    fused_gemm_ln_lrelu<<<NUM_TILES, THREADS, SMEM_TOTAL>>>(x, bias, gamma, beta, out);
}